// round 1
// baseline (speedup 1.0000x reference)
#include <cuda_runtime.h>

#define HWP 3600
#define NBATCH 2
#define CDIM 256
#define KNN 64
#define M_TOTAL (NBATCH*HWP)   // 7200
#define MPAD 7296              // padded rows (multiple of 128)

// ---------------- scratch (device globals; no allocation allowed) ----------
__device__ float g_hA[MPAD*CDIM];
__device__ float g_hB[MPAD*CDIM];
__device__ float g_m[MPAD*CDIM];
__device__ float g_tmp[MPAD*CDIM];
__device__ float g_msg[MPAD*CDIM];
__device__ int   g_idx[M_TOTAL*KNN];

__device__ __forceinline__ float4 ld4(const float* p){ return *reinterpret_cast<const float4*>(p); }
__device__ __forceinline__ void st4(float* p, float4 v){ *reinterpret_cast<float4*>(p) = v; }

// ---------------- init: h0 = NHWC view of cnn, out[:, :256] = cnn ----------
__global__ void __launch_bounds__(256) init_kernel(const float* __restrict__ cnn,
                                                   float* __restrict__ h0,
                                                   float* __restrict__ out)
{
    int e = blockIdx.x * 256 + threadIdx.x;          // 0 .. 2*256*3600-1
    int s = e % HWP;
    int c = (e / HWP) & (CDIM-1);
    int n = e / (HWP*CDIM);
    float v = cnn[e];
    out[(n*(2*CDIM) + c)*HWP + s] = v;               // coalesced
    h0[(n*HWP + s)*CDIM + c] = v;                    // scattered (small)
}

// ---------------- final: out[:, 256:512] = h (transposed back) -------------
__global__ void __launch_bounds__(256) final_kernel(const float* __restrict__ h,
                                                    float* __restrict__ out)
{
    int e = blockIdx.x * 256 + threadIdx.x;
    int s = e % HWP;
    int c = (e / HWP) & (CDIM-1);
    int n = e / (HWP*CDIM);
    out[(n*(2*CDIM) + CDIM + c)*HWP + s] = h[(n*HWP + s)*CDIM + c];
}

// ---------------- KNN: 64 smallest pairwise squared distances --------------
// One block handles 12 query rows of one batch. Distances kept in registers
// (15 per thread); k-th value found by 31-step bitwise binary search on the
// (non-negative) float bit pattern; set semantics (order irrelevant: the
// reference takes mean over the K neighbors).
#define KNN_BR 12
__global__ void __launch_bounds__(256) knn_kernel(const float* __restrict__ pts,
                                                  int* __restrict__ idx_out)
{
    __shared__ float px[HWP], py[HWP], pz[HWP];
    __shared__ int warp_sums[8];
    __shared__ int s_less, s_eqn;
    __shared__ int s_tie[256];

    int gb = blockIdx.x;
    int n  = gb / (HWP/KNN_BR);
    int g  = gb % (HWP/KNN_BR);
    int tid = threadIdx.x;

    const float* p = pts + n*3*HWP;
    for (int i = tid; i < HWP; i += 256) {
        px[i] = p[i];
        py[i] = p[i + HWP];
        pz[i] = p[i + 2*HWP];
    }
    __syncthreads();

    for (int r = 0; r < KNN_BR; ++r) {
        int row = g*KNN_BR + r;
        float qx = px[row], qy = py[row], qz = pz[row];
        float qs = fmaf(qz, qz, fmaf(qy, qy, qx*qx));

        unsigned d[15];
        #pragma unroll
        for (int t = 0; t < 15; ++t) {
            int j = t*256 + tid;
            if (j < HWP) {
                float x = px[j], y = py[j], z = pz[j];
                float sj  = fmaf(z, z, fmaf(y, y, x*x));
                float dot = fmaf(qz, z, fmaf(qy, y, qx*x));
                float f = fmaxf(qs + sj - 2.0f*dot, 0.0f);
                d[t] = __float_as_uint(f);
            } else {
                d[t] = 0x7f800000u;   // +inf padding
            }
        }

        // bitwise search for the 64th-smallest value V
        unsigned T = 0;
        for (int bit = 30; bit >= 0; --bit) {
            unsigned cand = T | (1u << bit);
            int c = 0;
            #pragma unroll
            for (int t = 0; t < 15; ++t) c += (d[t] < cand) ? 1 : 0;
            c = __reduce_add_sync(0xffffffffu, c);
            if ((tid & 31) == 0) warp_sums[tid >> 5] = c;
            __syncthreads();
            int tot = 0;
            #pragma unroll
            for (int w = 0; w < 8; ++w) tot += warp_sums[w];
            if (tot < KNN) T = cand;
            __syncthreads();
        }

        if (tid == 0) { s_less = 0; s_eqn = 0; }
        __syncthreads();

        int* outp = idx_out + (n*HWP + row)*KNN;
        #pragma unroll
        for (int t = 0; t < 15; ++t) {
            int j = t*256 + tid;
            unsigned dv = d[t];
            if (dv < T) {
                int pos = atomicAdd(&s_less, 1);
                outp[pos] = j;
            } else if (dv == T && j < HWP) {
                int pos = atomicAdd(&s_eqn, 1);
                if (pos < 256) s_tie[pos] = j;
            }
        }
        __syncthreads();
        if (tid == 0) {
            int slots = KNN - s_less;
            int en = s_eqn < 256 ? s_eqn : 256;
            for (int q = 0; q < slots; ++q) {      // lowest-index tie fill
                int best = 0x7fffffff, bi = 0;
                for (int e = 0; e < en; ++e)
                    if (s_tie[e] < best) { best = s_tie[e]; bi = e; }
                s_tie[bi] = 0x7fffffff;
                outp[s_less + q] = best;
            }
        }
        __syncthreads();
    }
}

// ---------------- shared GEMM mainloop (128x64 tile, 8x4/thread) -----------
__device__ __forceinline__ void stile(float* pa, float* pb, int kq, int lr,
                                      float4 a0, float4 a1, float4 b0)
{
    pa[(kq*4+0)*128 + lr] = a0.x;
    pa[(kq*4+1)*128 + lr] = a0.y;
    pa[(kq*4+2)*128 + lr] = a0.z;
    pa[(kq*4+3)*128 + lr] = a0.w;
    pa[(kq*4+0)*128 + 64 + lr] = a1.x;
    pa[(kq*4+1)*128 + 64 + lr] = a1.y;
    pa[(kq*4+2)*128 + 64 + lr] = a1.z;
    pa[(kq*4+3)*128 + 64 + lr] = a1.w;
    pb[(kq*4+0)*64 + lr] = b0.x;
    pb[(kq*4+1)*64 + lr] = b0.y;
    pb[(kq*4+2)*64 + lr] = b0.z;
    pb[(kq*4+3)*64 + lr] = b0.w;
}

__device__ __forceinline__ void gemm_mainloop(const float* __restrict__ A, int m0,
                                              const float* __restrict__ Wrow, int ldw,
                                              float4 acc[8])
{
    __shared__ float sA[2][16*128];
    __shared__ float sB[2][16*64];
    const int tid = threadIdx.x;
    const int kq  = tid & 3;
    const int lr  = tid >> 2;
    const int tmi = tid & 15;
    const int tni = tid >> 4;

    const float* ag0 = A + (m0 + lr)*CDIM + kq*4;
    const float* ag1 = ag0 + 64*CDIM;
    const float* bg  = Wrow + lr*ldw + kq*4;

    #pragma unroll
    for (int i = 0; i < 8; ++i) acc[i] = make_float4(0.f, 0.f, 0.f, 0.f);

    {
        float4 a0 = ld4(ag0), a1 = ld4(ag1), b0 = ld4(bg);
        stile(sA[0], sB[0], kq, lr, a0, a1, b0);
    }
    __syncthreads();

    #pragma unroll 1
    for (int kt = 0; kt < 16; ++kt) {
        const int cur = kt & 1;
        float4 na0, na1, nb0;
        if (kt < 15) {
            na0 = ld4(ag0 + (kt+1)*16);
            na1 = ld4(ag1 + (kt+1)*16);
            nb0 = ld4(bg  + (kt+1)*16);
        }
        const float* pa = sA[cur];
        const float* pb = sB[cur];
        #pragma unroll
        for (int k = 0; k < 16; ++k) {
            float4 x0 = ld4(pa + k*128 + tmi*4);
            float4 x1 = ld4(pa + k*128 + 64 + tmi*4);
            float4 bb = ld4(pb + k*64 + tni*4);
            float av0[4] = {x0.x, x0.y, x0.z, x0.w};
            float av1[4] = {x1.x, x1.y, x1.z, x1.w};
            #pragma unroll
            for (int i = 0; i < 4; ++i) {
                acc[i].x   = fmaf(av0[i], bb.x, acc[i].x);
                acc[i].y   = fmaf(av0[i], bb.y, acc[i].y);
                acc[i].z   = fmaf(av0[i], bb.z, acc[i].z);
                acc[i].w   = fmaf(av0[i], bb.w, acc[i].w);
                acc[i+4].x = fmaf(av1[i], bb.x, acc[i+4].x);
                acc[i+4].y = fmaf(av1[i], bb.y, acc[i+4].y);
                acc[i+4].z = fmaf(av1[i], bb.z, acc[i+4].z);
                acc[i+4].w = fmaf(av1[i], bb.w, acc[i+4].w);
            }
        }
        if (kt < 15) stile(sA[cur^1], sB[cur^1], kq, lr, na0, na1, nb0);
        __syncthreads();
    }
}

// GEMM1: m = relu(h W_mlp^T + b_mlp)  [by 0..3]  and  tmp = h W_a^T  [by 4..7]
__global__ void __launch_bounds__(256) gemm1_kernel(const float* __restrict__ A,
                                                    const float* __restrict__ mlp_w,
                                                    const float* __restrict__ rnn_w,
                                                    const float* __restrict__ mlp_b,
                                                    float* __restrict__ m_out,
                                                    float* __restrict__ tmp_out)
{
    int m0 = blockIdx.x * 128;
    int by = blockIdx.y;
    bool is_m = by < 4;
    int d0 = (is_m ? by : by - 4) * 64;
    const float* Wrow = is_m ? (mlp_w + d0*CDIM) : (rnn_w + d0*2*CDIM);
    int ldw = is_m ? CDIM : 2*CDIM;

    float4 acc[8];
    gemm_mainloop(A, m0, Wrow, ldw, acc);

    int tmi = threadIdx.x & 15, tni = threadIdx.x >> 4;
    int jq = d0 + tni*4;
    if (is_m) {
        float4 bb = ld4(mlp_b + jq);
        #pragma unroll
        for (int i = 0; i < 8; ++i) {
            int mr = m0 + ((i < 4) ? (tmi*4 + i) : (64 + tmi*4 + i - 4));
            if (mr < M_TOTAL) {
                float4 v;
                v.x = fmaxf(acc[i].x + bb.x, 0.f);
                v.y = fmaxf(acc[i].y + bb.y, 0.f);
                v.z = fmaxf(acc[i].z + bb.z, 0.f);
                v.w = fmaxf(acc[i].w + bb.w, 0.f);
                st4(m_out + mr*CDIM + jq, v);
            }
        }
    } else {
        #pragma unroll
        for (int i = 0; i < 8; ++i) {
            int mr = m0 + ((i < 4) ? (tmi*4 + i) : (64 + tmi*4 + i - 4));
            if (mr < M_TOTAL) st4(tmp_out + mr*CDIM + jq, acc[i]);
        }
    }
}

// GEMM3: h' = relu(tmp + msg W_b^T + b_rnn)
__global__ void __launch_bounds__(256) gemm3_kernel(const float* __restrict__ A,   // msg
                                                    const float* __restrict__ rnn_w,
                                                    const float* __restrict__ rnn_b,
                                                    const float* __restrict__ tmp,
                                                    float* __restrict__ h_out)
{
    int m0 = blockIdx.x * 128;
    int d0 = blockIdx.y * 64;
    const float* Wrow = rnn_w + d0*2*CDIM + CDIM;   // W_b half
    float4 acc[8];
    gemm_mainloop(A, m0, Wrow, 2*CDIM, acc);

    int tmi = threadIdx.x & 15, tni = threadIdx.x >> 4;
    int jq = d0 + tni*4;
    float4 bb = ld4(rnn_b + jq);
    #pragma unroll
    for (int i = 0; i < 8; ++i) {
        int mr = m0 + ((i < 4) ? (tmi*4 + i) : (64 + tmi*4 + i - 4));
        if (mr < M_TOTAL) {
            float4 t = ld4(tmp + mr*CDIM + jq);
            float4 v;
            v.x = fmaxf(acc[i].x + t.x + bb.x, 0.f);
            v.y = fmaxf(acc[i].y + t.y + bb.y, 0.f);
            v.z = fmaxf(acc[i].z + t.z + bb.z, 0.f);
            v.w = fmaxf(acc[i].w + t.w + bb.w, 0.f);
            st4(h_out + mr*CDIM + jq, v);
        }
    }
}

// ---------------- gather-mean: msg[s] = (1/64) sum_k m[idx[s][k]] ----------
__global__ void __launch_bounds__(256) gather_mean_kernel(const float* __restrict__ m,
                                                          const int* __restrict__ idx,
                                                          float* __restrict__ msg)
{
    __shared__ int sidx[4*KNN];
    int tid = threadIdx.x;
    int s0 = blockIdx.x * 4;
    sidx[tid] = idx[s0*KNN + tid];
    __syncthreads();

    int lp = tid >> 6;         // 0..3 local point
    int c4 = tid & 63;         // float4 column
    int s  = s0 + lp;
    int base = (s / HWP) * HWP;
    const float4* m4 = reinterpret_cast<const float4*>(m);
    const int* ip = sidx + lp*KNN;

    float4 a0 = make_float4(0,0,0,0), a1 = a0, a2 = a0, a3 = a0;
    #pragma unroll
    for (int k = 0; k < KNN; k += 4) {
        int j0 = ip[k], j1 = ip[k+1], j2 = ip[k+2], j3 = ip[k+3];
        float4 v0 = m4[(size_t)(base + j0)*64 + c4];
        float4 v1 = m4[(size_t)(base + j1)*64 + c4];
        float4 v2 = m4[(size_t)(base + j2)*64 + c4];
        float4 v3 = m4[(size_t)(base + j3)*64 + c4];
        a0.x += v0.x; a0.y += v0.y; a0.z += v0.z; a0.w += v0.w;
        a1.x += v1.x; a1.y += v1.y; a1.z += v1.z; a1.w += v1.w;
        a2.x += v2.x; a2.y += v2.y; a2.z += v2.z; a2.w += v2.w;
        a3.x += v3.x; a3.y += v3.y; a3.z += v3.z; a3.w += v3.w;
    }
    const float inv = 1.0f / 64.0f;
    float4 r;
    r.x = (a0.x + a1.x + a2.x + a3.x) * inv;
    r.y = (a0.y + a1.y + a2.y + a3.y) * inv;
    r.z = (a0.z + a1.z + a2.z + a3.z) * inv;
    r.w = (a0.w + a1.w + a2.w + a3.w) * inv;
    reinterpret_cast<float4*>(msg)[(size_t)s*64 + c4] = r;
}

// ---------------- launcher --------------------------------------------------
extern "C" void kernel_launch(void* const* d_in, const int* in_sizes, int n_in,
                              void* d_out, int out_size)
{
    const float* cnn   = (const float*)d_in[0];
    const float* pts   = (const float*)d_in[1];
    const float* mlp_w = (const float*)d_in[2];
    const float* mlp_b = (const float*)d_in[3];
    const float* rnn_w = (const float*)d_in[4];
    const float* rnn_b = (const float*)d_in[5];
    float* out = (float*)d_out;

    float *hA, *hB, *m, *tmp, *msg;
    int* idx;
    cudaGetSymbolAddress((void**)&hA,  g_hA);
    cudaGetSymbolAddress((void**)&hB,  g_hB);
    cudaGetSymbolAddress((void**)&m,   g_m);
    cudaGetSymbolAddress((void**)&tmp, g_tmp);
    cudaGetSymbolAddress((void**)&msg, g_msg);
    cudaGetSymbolAddress((void**)&idx, g_idx);

    init_kernel<<<(NBATCH*CDIM*HWP)/256, 256>>>(cnn, hA, out);
    knn_kernel<<<NBATCH*(HWP/KNN_BR), 256>>>(pts, idx);

    float* hc = hA;
    float* hn = hB;
    for (int it = 0; it < 3; ++it) {
        gemm1_kernel<<<dim3(57, 8), 256>>>(hc, mlp_w, rnn_w, mlp_b, m, tmp);
        gather_mean_kernel<<<M_TOTAL/4, 256>>>(m, idx, msg);
        gemm3_kernel<<<dim3(57, 4), 256>>>(msg, rnn_w, rnn_b, tmp, hn);
        float* t = hc; hc = hn; hn = t;
    }
    final_kernel<<<(NBATCH*CDIM*HWP)/256, 256>>>(hc, out);
}

// round 2
// speedup vs baseline: 1.0263x; 1.0263x over previous
#include <cuda_runtime.h>

#define HWP 3600
#define NBATCH 2
#define CDIM 256
#define KNN 64
#define M_TOTAL (NBATCH*HWP)   // 7200
#define MPAD 7296              // padded rows (multiple of 128)

#define BM 128
#define BN 64
#define BK 16

// ---------------- scratch (device globals; no allocation allowed) ----------
__device__ float g_hA[MPAD*CDIM];
__device__ float g_hB[MPAD*CDIM];
__device__ float g_m[MPAD*CDIM];
__device__ float g_tmp[MPAD*CDIM];
__device__ float g_msg[MPAD*CDIM];
__device__ int   g_idx[M_TOTAL*KNN];

__device__ __forceinline__ float4 ld4(const float* p){ return *reinterpret_cast<const float4*>(p); }
__device__ __forceinline__ void st4(float* p, float4 v){ *reinterpret_cast<float4*>(p) = v; }

// packed f32x2 FMA: d = a*b + c on both 32-bit lanes (exact fp32, 2x rate)
__device__ __forceinline__ unsigned long long fma2(unsigned long long a,
                                                   unsigned long long b,
                                                   unsigned long long c){
    unsigned long long d;
    asm("fma.rn.f32x2 %0, %1, %2, %3;" : "=l"(d) : "l"(a), "l"(b), "l"(c));
    return d;
}
__device__ __forceinline__ unsigned long long dup32(float b){
    unsigned long long d;
    asm("mov.b64 %0, {%1, %1};" : "=l"(d) : "f"(b));
    return d;
}
__device__ __forceinline__ float lo32(unsigned long long v){ return __uint_as_float((unsigned)v); }
__device__ __forceinline__ float hi32(unsigned long long v){ return __uint_as_float((unsigned)(v>>32)); }

// ---------------- init: h0 = NHWC view of cnn, out[:, :256] = cnn ----------
__global__ void __launch_bounds__(256) init_kernel(const float* __restrict__ cnn,
                                                   float* __restrict__ h0,
                                                   float* __restrict__ out)
{
    int e = blockIdx.x * 256 + threadIdx.x;
    int s = e % HWP;
    int c = (e / HWP) & (CDIM-1);
    int n = e / (HWP*CDIM);
    float v = cnn[e];
    out[(n*(2*CDIM) + c)*HWP + s] = v;
    h0[(n*HWP + s)*CDIM + c] = v;
}

__global__ void __launch_bounds__(256) final_kernel(const float* __restrict__ h,
                                                    float* __restrict__ out)
{
    int e = blockIdx.x * 256 + threadIdx.x;
    int s = e % HWP;
    int c = (e / HWP) & (CDIM-1);
    int n = e / (HWP*CDIM);
    out[(n*(2*CDIM) + CDIM + c)*HWP + s] = h[(n*HWP + s)*CDIM + c];
}

// ---------------- KNN (one barrier per bit via parity buffers) -------------
#define KNN_BR 12
__global__ void __launch_bounds__(256) knn_kernel(const float* __restrict__ pts,
                                                  int* __restrict__ idx_out)
{
    __shared__ float px[HWP], py[HWP], pz[HWP];
    __shared__ int warp_sums[2][8];
    __shared__ int s_less, s_eqn;
    __shared__ int s_tie[256];

    int gb = blockIdx.x;
    int n  = gb / (HWP/KNN_BR);
    int g  = gb % (HWP/KNN_BR);
    int tid = threadIdx.x;

    const float* p = pts + n*3*HWP;
    for (int i = tid; i < HWP; i += 256) {
        px[i] = p[i];
        py[i] = p[i + HWP];
        pz[i] = p[i + 2*HWP];
    }
    __syncthreads();

    for (int r = 0; r < KNN_BR; ++r) {
        int row = g*KNN_BR + r;
        float qx = px[row], qy = py[row], qz = pz[row];
        float qs = fmaf(qz, qz, fmaf(qy, qy, qx*qx));

        unsigned d[15];
        #pragma unroll
        for (int t = 0; t < 15; ++t) {
            int j = t*256 + tid;
            if (j < HWP) {
                float x = px[j], y = py[j], z = pz[j];
                float sj  = fmaf(z, z, fmaf(y, y, x*x));
                float dot = fmaf(qz, z, fmaf(qy, y, qx*x));
                float f = fmaxf(qs + sj - 2.0f*dot, 0.0f);
                d[t] = __float_as_uint(f);
            } else {
                d[t] = 0x7f800000u;
            }
        }

        unsigned T = 0;
        for (int bit = 30; bit >= 0; --bit) {
            unsigned cand = T | (1u << bit);
            int c = 0;
            #pragma unroll
            for (int t = 0; t < 15; ++t) c += (d[t] < cand) ? 1 : 0;
            c = __reduce_add_sync(0xffffffffu, c);
            int par = bit & 1;
            if ((tid & 31) == 0) warp_sums[par][tid >> 5] = c;
            __syncthreads();
            int tot = 0;
            #pragma unroll
            for (int w = 0; w < 8; ++w) tot += warp_sums[par][w];
            if (tot < KNN) T = cand;
        }

        __syncthreads();
        if (tid == 0) { s_less = 0; s_eqn = 0; }
        __syncthreads();

        int* outp = idx_out + (n*HWP + row)*KNN;
        #pragma unroll
        for (int t = 0; t < 15; ++t) {
            int j = t*256 + tid;
            unsigned dv = d[t];
            if (dv < T) {
                int pos = atomicAdd(&s_less, 1);
                outp[pos] = j;
            } else if (dv == T && j < HWP) {
                int pos = atomicAdd(&s_eqn, 1);
                if (pos < 256) s_tie[pos] = j;
            }
        }
        __syncthreads();
        if (tid == 0) {
            int slots = KNN - s_less;
            int en = s_eqn < 256 ? s_eqn : 256;
            for (int q = 0; q < slots; ++q) {
                int best = 0x7fffffff, bi = 0;
                for (int e = 0; e < en; ++e)
                    if (s_tie[e] < best) { best = s_tie[e]; bi = e; }
                s_tie[bi] = 0x7fffffff;
                outp[s_less + q] = best;
            }
        }
        __syncthreads();
    }
}

// ---------------- GEMM mainloop: 128x64 tile, 8m x 4n per thread, FFMA2 ----
// acc[mp][j]: packed pair (m = ty*8 + mp*2 (+1 in hi lane)), n = tx*4 + j
__device__ __forceinline__ void gemm_mainloop(const float* __restrict__ A, int m0,
                                              const float* __restrict__ Wrow, int ldw,
                                              unsigned long long acc[4][4])
{
    __shared__ float sA[2][BK][BM];
    __shared__ float sB[2][BK][BN];
    const int tid  = threadIdx.x;
    const int arow = tid & 127, akq = tid >> 7;   // A items: (akq, akq+2)
    const int brow = tid & 63,  bkq = tid >> 6;
    const int tx = tid & 15, ty = tid >> 4;

    const float* agp = A + (m0 + arow)*CDIM + akq*4;
    const float* bgp = Wrow + brow*ldw + bkq*4;

    #pragma unroll
    for (int i = 0; i < 4; ++i)
        #pragma unroll
        for (int j = 0; j < 4; ++j) acc[i][j] = 0ull;

    // prologue: fill buffer 0
    {
        float4 a0 = ld4(agp), a1 = ld4(agp + 8), b0 = ld4(bgp);
        sA[0][akq*4+0][arow] = a0.x; sA[0][akq*4+1][arow] = a0.y;
        sA[0][akq*4+2][arow] = a0.z; sA[0][akq*4+3][arow] = a0.w;
        sA[0][(akq+2)*4+0][arow] = a1.x; sA[0][(akq+2)*4+1][arow] = a1.y;
        sA[0][(akq+2)*4+2][arow] = a1.z; sA[0][(akq+2)*4+3][arow] = a1.w;
        sB[0][bkq*4+0][brow] = b0.x; sB[0][bkq*4+1][brow] = b0.y;
        sB[0][bkq*4+2][brow] = b0.z; sB[0][bkq*4+3][brow] = b0.w;
    }
    __syncthreads();

    #pragma unroll 1
    for (int kt = 0; kt < CDIM/BK; ++kt) {
        const int cur = kt & 1;
        float4 na0, na1, nb0;
        if (kt < CDIM/BK - 1) {
            na0 = ld4(agp + (kt+1)*BK);
            na1 = ld4(agp + (kt+1)*BK + 8);
            nb0 = ld4(bgp + (kt+1)*BK);
        }
        #pragma unroll
        for (int k = 0; k < BK; ++k) {
            ulonglong2 a01 = *reinterpret_cast<const ulonglong2*>(&sA[cur][k][ty*8]);
            ulonglong2 a23 = *reinterpret_cast<const ulonglong2*>(&sA[cur][k][ty*8+4]);
            float4 b = ld4(&sB[cur][k][tx*4]);
            unsigned long long bd0 = dup32(b.x), bd1 = dup32(b.y),
                               bd2 = dup32(b.z), bd3 = dup32(b.w);
            acc[0][0] = fma2(a01.x, bd0, acc[0][0]);
            acc[0][1] = fma2(a01.x, bd1, acc[0][1]);
            acc[0][2] = fma2(a01.x, bd2, acc[0][2]);
            acc[0][3] = fma2(a01.x, bd3, acc[0][3]);
            acc[1][0] = fma2(a01.y, bd0, acc[1][0]);
            acc[1][1] = fma2(a01.y, bd1, acc[1][1]);
            acc[1][2] = fma2(a01.y, bd2, acc[1][2]);
            acc[1][3] = fma2(a01.y, bd3, acc[1][3]);
            acc[2][0] = fma2(a23.x, bd0, acc[2][0]);
            acc[2][1] = fma2(a23.x, bd1, acc[2][1]);
            acc[2][2] = fma2(a23.x, bd2, acc[2][2]);
            acc[2][3] = fma2(a23.x, bd3, acc[2][3]);
            acc[3][0] = fma2(a23.y, bd0, acc[3][0]);
            acc[3][1] = fma2(a23.y, bd1, acc[3][1]);
            acc[3][2] = fma2(a23.y, bd2, acc[3][2]);
            acc[3][3] = fma2(a23.y, bd3, acc[3][3]);
        }
        if (kt < CDIM/BK - 1) {
            const int nxt = cur ^ 1;
            sA[nxt][akq*4+0][arow] = na0.x; sA[nxt][akq*4+1][arow] = na0.y;
            sA[nxt][akq*4+2][arow] = na0.z; sA[nxt][akq*4+3][arow] = na0.w;
            sA[nxt][(akq+2)*4+0][arow] = na1.x; sA[nxt][(akq+2)*4+1][arow] = na1.y;
            sA[nxt][(akq+2)*4+2][arow] = na1.z; sA[nxt][(akq+2)*4+3][arow] = na1.w;
            sB[nxt][bkq*4+0][brow] = nb0.x; sB[nxt][bkq*4+1][brow] = nb0.y;
            sB[nxt][bkq*4+2][brow] = nb0.z; sB[nxt][bkq*4+3][brow] = nb0.w;
        }
        __syncthreads();
    }
}

// GEMM1: m = relu(h W_mlp^T + b_mlp)  [by 0..3]  and  tmp = h W_a^T  [by 4..7]
__global__ void __launch_bounds__(256) gemm1_kernel(const float* __restrict__ A,
                                                    const float* __restrict__ mlp_w,
                                                    const float* __restrict__ rnn_w,
                                                    const float* __restrict__ mlp_b,
                                                    float* __restrict__ m_out,
                                                    float* __restrict__ tmp_out)
{
    int m0 = blockIdx.x * BM;
    int by = blockIdx.y;
    bool is_m = by < 4;
    int d0 = (is_m ? by : by - 4) * BN;
    const float* Wrow = is_m ? (mlp_w + d0*CDIM) : (rnn_w + d0*2*CDIM);
    int ldw = is_m ? CDIM : 2*CDIM;

    unsigned long long acc[4][4];
    gemm_mainloop(A, m0, Wrow, ldw, acc);

    int tx = threadIdx.x & 15, ty = threadIdx.x >> 4;
    int jq = d0 + tx*4;
    if (is_m) {
        float4 bb = ld4(mlp_b + jq);
        #pragma unroll
        for (int r = 0; r < 8; ++r) {
            int mp = r >> 1; bool hi = r & 1;
            float4 v;
            v.x = (hi ? hi32(acc[mp][0]) : lo32(acc[mp][0])) + bb.x;
            v.y = (hi ? hi32(acc[mp][1]) : lo32(acc[mp][1])) + bb.y;
            v.z = (hi ? hi32(acc[mp][2]) : lo32(acc[mp][2])) + bb.z;
            v.w = (hi ? hi32(acc[mp][3]) : lo32(acc[mp][3])) + bb.w;
            v.x = fmaxf(v.x, 0.f); v.y = fmaxf(v.y, 0.f);
            v.z = fmaxf(v.z, 0.f); v.w = fmaxf(v.w, 0.f);
            st4(m_out + (m0 + ty*8 + r)*CDIM + jq, v);
        }
    } else {
        #pragma unroll
        for (int r = 0; r < 8; ++r) {
            int mp = r >> 1; bool hi = r & 1;
            float4 v;
            v.x = hi ? hi32(acc[mp][0]) : lo32(acc[mp][0]);
            v.y = hi ? hi32(acc[mp][1]) : lo32(acc[mp][1]);
            v.z = hi ? hi32(acc[mp][2]) : lo32(acc[mp][2]);
            v.w = hi ? hi32(acc[mp][3]) : lo32(acc[mp][3]);
            st4(tmp_out + (m0 + ty*8 + r)*CDIM + jq, v);
        }
    }
}

// GEMM3: h' = relu(tmp + msg W_b^T + b_rnn)
__global__ void __launch_bounds__(256) gemm3_kernel(const float* __restrict__ A,
                                                    const float* __restrict__ rnn_w,
                                                    const float* __restrict__ rnn_b,
                                                    const float* __restrict__ tmp,
                                                    float* __restrict__ h_out)
{
    int m0 = blockIdx.x * BM;
    int d0 = blockIdx.y * BN;
    const float* Wrow = rnn_w + d0*2*CDIM + CDIM;   // W_b half
    unsigned long long acc[4][4];
    gemm_mainloop(A, m0, Wrow, 2*CDIM, acc);

    int tx = threadIdx.x & 15, ty = threadIdx.x >> 4;
    int jq = d0 + tx*4;
    float4 bb = ld4(rnn_b + jq);
    #pragma unroll
    for (int r = 0; r < 8; ++r) {
        int mp = r >> 1; bool hi = r & 1;
        int mr = m0 + ty*8 + r;
        float4 t = ld4(tmp + mr*CDIM + jq);
        float4 v;
        v.x = fmaxf((hi ? hi32(acc[mp][0]) : lo32(acc[mp][0])) + t.x + bb.x, 0.f);
        v.y = fmaxf((hi ? hi32(acc[mp][1]) : lo32(acc[mp][1])) + t.y + bb.y, 0.f);
        v.z = fmaxf((hi ? hi32(acc[mp][2]) : lo32(acc[mp][2])) + t.z + bb.z, 0.f);
        v.w = fmaxf((hi ? hi32(acc[mp][3]) : lo32(acc[mp][3])) + t.w + bb.w, 0.f);
        st4(h_out + mr*CDIM + jq, v);
    }
}

// ---------------- gather-mean: 8 points per block for L1 neighbor overlap --
__global__ void __launch_bounds__(512) gather_mean_kernel(const float* __restrict__ m,
                                                          const int* __restrict__ idx,
                                                          float* __restrict__ msg)
{
    __shared__ int sidx[8*KNN];
    int tid = threadIdx.x;
    int s0 = blockIdx.x * 8;
    sidx[tid] = idx[s0*KNN + tid];
    __syncthreads();

    int lp = tid >> 6;         // 0..7 local point
    int c4 = tid & 63;         // float4 column
    int s  = s0 + lp;
    int base = (s / HWP) * HWP;
    const float4* m4 = reinterpret_cast<const float4*>(m);
    const int* ip = sidx + lp*KNN;

    float4 a0 = make_float4(0,0,0,0), a1 = a0, a2 = a0, a3 = a0;
    #pragma unroll
    for (int k = 0; k < KNN; k += 4) {
        int j0 = ip[k], j1 = ip[k+1], j2 = ip[k+2], j3 = ip[k+3];
        float4 v0 = m4[(size_t)(base + j0)*64 + c4];
        float4 v1 = m4[(size_t)(base + j1)*64 + c4];
        float4 v2 = m4[(size_t)(base + j2)*64 + c4];
        float4 v3 = m4[(size_t)(base + j3)*64 + c4];
        a0.x += v0.x; a0.y += v0.y; a0.z += v0.z; a0.w += v0.w;
        a1.x += v1.x; a1.y += v1.y; a1.z += v1.z; a1.w += v1.w;
        a2.x += v2.x; a2.y += v2.y; a2.z += v2.z; a2.w += v2.w;
        a3.x += v3.x; a3.y += v3.y; a3.z += v3.z; a3.w += v3.w;
    }
    const float inv = 1.0f / 64.0f;
    float4 r;
    r.x = (a0.x + a1.x + a2.x + a3.x) * inv;
    r.y = (a0.y + a1.y + a2.y + a3.y) * inv;
    r.z = (a0.z + a1.z + a2.z + a3.z) * inv;
    r.w = (a0.w + a1.w + a2.w + a3.w) * inv;
    reinterpret_cast<float4*>(msg)[(size_t)s*64 + c4] = r;
}

// ---------------- launcher --------------------------------------------------
extern "C" void kernel_launch(void* const* d_in, const int* in_sizes, int n_in,
                              void* d_out, int out_size)
{
    const float* cnn   = (const float*)d_in[0];
    const float* pts   = (const float*)d_in[1];
    const float* mlp_w = (const float*)d_in[2];
    const float* mlp_b = (const float*)d_in[3];
    const float* rnn_w = (const float*)d_in[4];
    const float* rnn_b = (const float*)d_in[5];
    float* out = (float*)d_out;

    float *hA, *hB, *m, *tmp, *msg;
    int* idx;
    cudaGetSymbolAddress((void**)&hA,  g_hA);
    cudaGetSymbolAddress((void**)&hB,  g_hB);
    cudaGetSymbolAddress((void**)&m,   g_m);
    cudaGetSymbolAddress((void**)&tmp, g_tmp);
    cudaGetSymbolAddress((void**)&msg, g_msg);
    cudaGetSymbolAddress((void**)&idx, g_idx);

    init_kernel<<<(NBATCH*CDIM*HWP)/256, 256>>>(cnn, hA, out);
    knn_kernel<<<NBATCH*(HWP/KNN_BR), 256>>>(pts, idx);

    float* hc = hA;
    float* hn = hB;
    for (int it = 0; it < 3; ++it) {
        gemm1_kernel<<<dim3(57, 8), 256>>>(hc, mlp_w, rnn_w, mlp_b, m, tmp);
        gather_mean_kernel<<<M_TOTAL/8, 512>>>(m, idx, msg);
        gemm3_kernel<<<dim3(57, 4), 256>>>(msg, rnn_w, rnn_b, tmp, hn);
        float* t = hc; hc = hn; hn = t;
    }
    final_kernel<<<(NBATCH*CDIM*HWP)/256, 256>>>(hc, out);
}

// round 4
// speedup vs baseline: 1.3465x; 1.3120x over previous
#include <cuda_runtime.h>
#include <cuda_bf16.h>
#include <cstdint>

#define HWP 3600
#define NBATCH 2
#define CDIM 256
#define KNN 64
#define M_TOTAL (NBATCH*HWP)   // 7200
#define MPAD 7296              // padded rows (multiple of 128)

// ---------------- scratch (device globals; no allocation allowed) ----------
__device__ float g_m[MPAD*CDIM];        // relu(mlp(h)) fp32
__device__ float g_tmp[MPAD*CDIM];      // h @ Wa^T fp32
__device__ float g_h[MPAD*CDIM];        // fp32 h (for final readout)
__device__ __nv_bfloat16 g_Ah[MPAD*CDIM], g_Al[MPAD*CDIM];   // h split
__device__ __nv_bfloat16 g_Mh[MPAD*CDIM], g_Ml[MPAD*CDIM];   // msg split
__device__ __nv_bfloat16 g_Wmh[CDIM*CDIM], g_Wml[CDIM*CDIM]; // mlp_w split
__device__ __nv_bfloat16 g_Wah[CDIM*CDIM], g_Wal[CDIM*CDIM]; // rnn_w[:, :C]
__device__ __nv_bfloat16 g_Wbh[CDIM*CDIM], g_Wbl[CDIM*CDIM]; // rnn_w[:, C:]
__device__ int   g_idx[M_TOTAL*KNN];

__device__ __forceinline__ float4 ld4(const float* p){ return *reinterpret_cast<const float4*>(p); }
__device__ __forceinline__ void st4(float* p, float4 v){ *reinterpret_cast<float4*>(p) = v; }

__device__ __forceinline__ void bsplit(float v, __nv_bfloat16& h, __nv_bfloat16& l){
    h = __float2bfloat16(v);
    l = __float2bfloat16(v - __bfloat162float(h));
}

__device__ __forceinline__ uint32_t smem_u32(const void* p) {
    uint32_t a;
    asm("{ .reg .u64 t; cvta.to.shared.u64 t, %1; cvt.u32.u64 %0, t; }" : "=r"(a) : "l"(p));
    return a;
}

// ---------------- mma.sync helpers (suffix-neutral PTX, tensor pipe) -------
__device__ __forceinline__ void ldmat4(uint32_t r[4], uint32_t addr){
    asm volatile("ldmatrix.sync.aligned.m8n8.x4.shared.b16 {%0,%1,%2,%3}, [%4];"
        : "=r"(r[0]), "=r"(r[1]), "=r"(r[2]), "=r"(r[3]) : "r"(addr));
}
__device__ __forceinline__ void mma16816(float c[4], const uint32_t a[4],
                                         uint32_t b0, uint32_t b1){
    asm volatile("mma.sync.aligned.m16n8k16.row.col.f32.bf16.bf16.f32 "
        "{%0,%1,%2,%3}, {%4,%5,%6,%7}, {%8,%9}, {%0,%1,%2,%3};"
        : "+f"(c[0]), "+f"(c[1]), "+f"(c[2]), "+f"(c[3])
        : "r"(a[0]), "r"(a[1]), "r"(a[2]), "r"(a[3]), "r"(b0), "r"(b1));
}

// smem tile layout: padded stride 72 bf16 (144B = 9 x 16B -> conflict-free)
#define ASTRIDE 72
#define OFF_AH  0
#define OFF_AL  18432
#define OFF_BH  36864
#define OFF_BL  46080
#define GEMM_SMEM 55296

// ---- 128x64x256 tile: bf16 3-term split via mma.sync, fp32 accumulate -----
// Bh/Bl pre-offset to output-row d0. acc[mt][nt][q] per warp.
__device__ void tile_mma(const __nv_bfloat16* __restrict__ Ah,
                         const __nv_bfloat16* __restrict__ Al,
                         const __nv_bfloat16* __restrict__ Bh,
                         const __nv_bfloat16* __restrict__ Bl,
                         int m0, float acc[2][4][4])
{
    extern __shared__ char smem[];
    const uint32_t sb = smem_u32(smem);
    const int tid = threadIdx.x;
    const int lane = tid & 31;
    const int wid = tid >> 5;
    const int wm = wid & 3;        // m32 section
    const int wn = wid >> 2;       // n32 section

    #pragma unroll
    for (int mt = 0; mt < 2; ++mt)
        #pragma unroll
        for (int nt = 0; nt < 4; ++nt)
            #pragma unroll
            for (int q = 0; q < 4; ++q) acc[mt][nt][q] = 0.f;

    // ldmatrix per-lane offsets (bytes)
    const uint32_t aoff = (uint32_t)(((lane & 15)*ASTRIDE + (lane >> 4)*8) * 2);
    const uint32_t boff = (uint32_t)((((lane & 7) + ((lane >> 4) << 3))*ASTRIDE
                                      + ((lane >> 3) & 1)*8) * 2);

    #pragma unroll 1
    for (int kc = 0; kc < 4; ++kc) {
        // ---- copy chunk kc (k-range kc*64..+63) into smem ----
        #pragma unroll
        for (int i = 0; i < 12; ++i) {
            int v = tid + i*256;
            const uint4* src;
            uint32_t dst;
            if (v < 1024) {
                int row = v >> 3, c8 = v & 7;
                src = (const uint4*)(Ah + (m0 + row)*CDIM + kc*64 + c8*8);
                dst = OFF_AH + (uint32_t)(row*ASTRIDE + c8*8)*2;
            } else if (v < 2048) {
                int u = v - 1024, row = u >> 3, c8 = u & 7;
                src = (const uint4*)(Al + (m0 + row)*CDIM + kc*64 + c8*8);
                dst = OFF_AL + (uint32_t)(row*ASTRIDE + c8*8)*2;
            } else if (v < 2560) {
                int u = v - 2048, row = u >> 3, c8 = u & 7;
                src = (const uint4*)(Bh + row*CDIM + kc*64 + c8*8);
                dst = OFF_BH + (uint32_t)(row*ASTRIDE + c8*8)*2;
            } else {
                int u = v - 2560, row = u >> 3, c8 = u & 7;
                src = (const uint4*)(Bl + row*CDIM + kc*64 + c8*8);
                dst = OFF_BL + (uint32_t)(row*ASTRIDE + c8*8)*2;
            }
            *(uint4*)(smem + dst) = *src;
        }
        __syncthreads();

        // ---- 4 k16 steps of MMA ----
        #pragma unroll
        for (int ks = 0; ks < 4; ++ks) {
            const uint32_t abase = (uint32_t)((wm*32*ASTRIDE + ks*16) * 2);
            const uint32_t bbase = (uint32_t)((wn*32*ASTRIDE + ks*16) * 2);
            const uint32_t mstep = (uint32_t)(16*ASTRIDE*2);

            uint32_t ah0[4], ah1[4], al0[4], al1[4];
            ldmat4(ah0, sb + OFF_AH + abase + aoff);
            ldmat4(ah1, sb + OFF_AH + abase + mstep + aoff);
            ldmat4(al0, sb + OFF_AL + abase + aoff);
            ldmat4(al1, sb + OFF_AL + abase + mstep + aoff);

            uint32_t bhA[4], bhB[4], blA[4], blB[4];
            ldmat4(bhA, sb + OFF_BH + bbase + boff);
            ldmat4(bhB, sb + OFF_BH + bbase + mstep + boff);
            ldmat4(blA, sb + OFF_BL + bbase + boff);
            ldmat4(blB, sb + OFF_BL + bbase + mstep + boff);

            // ah*bh
            mma16816(acc[0][0], ah0, bhA[0], bhA[1]);
            mma16816(acc[0][1], ah0, bhA[2], bhA[3]);
            mma16816(acc[0][2], ah0, bhB[0], bhB[1]);
            mma16816(acc[0][3], ah0, bhB[2], bhB[3]);
            mma16816(acc[1][0], ah1, bhA[0], bhA[1]);
            mma16816(acc[1][1], ah1, bhA[2], bhA[3]);
            mma16816(acc[1][2], ah1, bhB[0], bhB[1]);
            mma16816(acc[1][3], ah1, bhB[2], bhB[3]);
            // ah*bl
            mma16816(acc[0][0], ah0, blA[0], blA[1]);
            mma16816(acc[0][1], ah0, blA[2], blA[3]);
            mma16816(acc[0][2], ah0, blB[0], blB[1]);
            mma16816(acc[0][3], ah0, blB[2], blB[3]);
            mma16816(acc[1][0], ah1, blA[0], blA[1]);
            mma16816(acc[1][1], ah1, blA[2], blA[3]);
            mma16816(acc[1][2], ah1, blB[0], blB[1]);
            mma16816(acc[1][3], ah1, blB[2], blB[3]);
            // al*bh
            mma16816(acc[0][0], al0, bhA[0], bhA[1]);
            mma16816(acc[0][1], al0, bhA[2], bhA[3]);
            mma16816(acc[0][2], al0, bhB[0], bhB[1]);
            mma16816(acc[0][3], al0, bhB[2], bhB[3]);
            mma16816(acc[1][0], al1, bhA[0], bhA[1]);
            mma16816(acc[1][1], al1, bhA[2], bhA[3]);
            mma16816(acc[1][2], al1, bhB[0], bhB[1]);
            mma16816(acc[1][3], al1, bhB[2], bhB[3]);
        }
        __syncthreads();
    }
}

// GEMM1: by 0..3 -> m = relu(h Wmlp^T + b);  by 4..7 -> tmp = h Wa^T
__global__ void __launch_bounds__(256) gemm1_kernel(const float* __restrict__ mlp_b,
                                                    float* __restrict__ m_out,
                                                    float* __restrict__ tmp_out)
{
    int m0 = blockIdx.x * 128;
    int by = blockIdx.y;
    bool is_m = by < 4;
    int d0 = (is_m ? by : by - 4) * 64;
    const __nv_bfloat16* Bh = (is_m ? g_Wmh : g_Wah) + d0*CDIM;
    const __nv_bfloat16* Bl = (is_m ? g_Wml : g_Wal) + d0*CDIM;

    float acc[2][4][4];
    tile_mma(g_Ah, g_Al, Bh, Bl, m0, acc);

    int lane = threadIdx.x & 31, wid = threadIdx.x >> 5;
    int wm = wid & 3, wn = wid >> 2;
    int g = lane >> 2, t = lane & 3;

    #pragma unroll
    for (int mt = 0; mt < 2; ++mt) {
        #pragma unroll
        for (int nt = 0; nt < 4; ++nt) {
            int nl = wn*32 + nt*8 + t*2;
            int n = d0 + nl;
            float bx = 0.f, byv = 0.f;
            if (is_m) { bx = mlp_b[n]; byv = mlp_b[n+1]; }
            #pragma unroll
            for (int half = 0; half < 2; ++half) {
                int m = m0 + wm*32 + mt*16 + g + half*8;
                if (m >= M_TOTAL) continue;
                float vx = acc[mt][nt][half*2+0];
                float vy = acc[mt][nt][half*2+1];
                if (is_m) {
                    vx = fmaxf(vx + bx, 0.f);
                    vy = fmaxf(vy + byv, 0.f);
                    *(float2*)(m_out + m*CDIM + n) = make_float2(vx, vy);
                } else {
                    *(float2*)(tmp_out + m*CDIM + n) = make_float2(vx, vy);
                }
            }
        }
    }
}

// GEMM3: h' = relu(tmp + msg Wb^T + b_rnn); writes fp32 h and bf16 split
__global__ void __launch_bounds__(256) gemm3_kernel(const float* __restrict__ rnn_b,
                                                    const float* __restrict__ tmp,
                                                    float* __restrict__ h_out)
{
    int m0 = blockIdx.x * 128;
    int d0 = blockIdx.y * 64;

    float acc[2][4][4];
    tile_mma(g_Mh, g_Ml, g_Wbh + d0*CDIM, g_Wbl + d0*CDIM, m0, acc);

    int lane = threadIdx.x & 31, wid = threadIdx.x >> 5;
    int wm = wid & 3, wn = wid >> 2;
    int g = lane >> 2, t = lane & 3;

    #pragma unroll
    for (int mt = 0; mt < 2; ++mt) {
        #pragma unroll
        for (int nt = 0; nt < 4; ++nt) {
            int n = d0 + wn*32 + nt*8 + t*2;
            float bx = rnn_b[n], byv = rnn_b[n+1];
            #pragma unroll
            for (int half = 0; half < 2; ++half) {
                int m = m0 + wm*32 + mt*16 + g + half*8;
                if (m >= M_TOTAL) continue;
                float2 tv = *(const float2*)(tmp + m*CDIM + n);
                float vx = fmaxf(acc[mt][nt][half*2+0] + tv.x + bx, 0.f);
                float vy = fmaxf(acc[mt][nt][half*2+1] + tv.y + byv, 0.f);
                *(float2*)(h_out + m*CDIM + n) = make_float2(vx, vy);
                __nv_bfloat16 hx, lx, hy, ly;
                bsplit(vx, hx, lx); bsplit(vy, hy, ly);
                *(__nv_bfloat162*)(g_Ah + m*CDIM + n) = __nv_bfloat162(hx, hy);
                *(__nv_bfloat162*)(g_Al + m*CDIM + n) = __nv_bfloat162(lx, ly);
            }
        }
    }
}

// ---------------- weight conversion (once per call) ------------------------
__global__ void __launch_bounds__(256) wconv_kernel(const float* __restrict__ mlp_w,
                                                    const float* __restrict__ rnn_w)
{
    int e = blockIdx.x * 256 + threadIdx.x;   // < 256*768
    if (e < CDIM*CDIM) {
        __nv_bfloat16 h, l; bsplit(mlp_w[e], h, l);
        g_Wmh[e] = h; g_Wml[e] = l;
    } else {
        int u = e - CDIM*CDIM;                 // < 256*512
        int r = u >> 9, c = u & 511;
        __nv_bfloat16 h, l; bsplit(rnn_w[u], h, l);
        if (c < CDIM) { g_Wah[r*CDIM + c] = h; g_Wal[r*CDIM + c] = l; }
        else          { g_Wbh[r*CDIM + c - CDIM] = h; g_Wbl[r*CDIM + c - CDIM] = l; }
    }
}

// zero padded rows of bf16 operand arrays
__global__ void __launch_bounds__(256) pad_kernel()
{
    int e = blockIdx.x * 256 + threadIdx.x;   // < 96*256
    int o = (M_TOTAL + (e >> 8))*CDIM + (e & 255);
    g_Ah[o] = __float2bfloat16(0.f); g_Al[o] = __float2bfloat16(0.f);
    g_Mh[o] = __float2bfloat16(0.f); g_Ml[o] = __float2bfloat16(0.f);
}

// ---------------- init: out[:, :256] = cnn; Ah/Al = bf16 split of NHWC h0 --
__global__ void __launch_bounds__(256) init_kernel(const float* __restrict__ cnn,
                                                   float* __restrict__ out)
{
    int e = blockIdx.x * 256 + threadIdx.x;
    int s = e % HWP;
    int c = (e / HWP) & (CDIM-1);
    int n = e / (HWP*CDIM);
    float v = cnn[e];
    out[(n*(2*CDIM) + c)*HWP + s] = v;
    __nv_bfloat16 h, l; bsplit(v, h, l);
    int o = (n*HWP + s)*CDIM + c;
    g_Ah[o] = h; g_Al[o] = l;
}

__global__ void __launch_bounds__(256) final_kernel(const float* __restrict__ h,
                                                    float* __restrict__ out)
{
    int e = blockIdx.x * 256 + threadIdx.x;
    int s = e % HWP;
    int c = (e / HWP) & (CDIM-1);
    int n = e / (HWP*CDIM);
    out[(n*(2*CDIM) + CDIM + c)*HWP + s] = h[(n*HWP + s)*CDIM + c];
}

// ---------------- KNN --------------------------------------------------------
#define KNN_BR 12
__global__ void __launch_bounds__(256) knn_kernel(const float* __restrict__ pts,
                                                  int* __restrict__ idx_out)
{
    __shared__ float px[HWP], py[HWP], pz[HWP];
    __shared__ int warp_sums[2][8];
    __shared__ int s_less, s_eqn;
    __shared__ int s_tie[256];

    int gb = blockIdx.x;
    int n  = gb / (HWP/KNN_BR);
    int g  = gb % (HWP/KNN_BR);
    int tid = threadIdx.x;

    const float* p = pts + n*3*HWP;
    for (int i = tid; i < HWP; i += 256) {
        px[i] = p[i];
        py[i] = p[i + HWP];
        pz[i] = p[i + 2*HWP];
    }
    __syncthreads();

    for (int r = 0; r < KNN_BR; ++r) {
        int row = g*KNN_BR + r;
        float qx = px[row], qy = py[row], qz = pz[row];
        float qs = fmaf(qz, qz, fmaf(qy, qy, qx*qx));

        unsigned d[15];
        #pragma unroll
        for (int t = 0; t < 15; ++t) {
            int j = t*256 + tid;
            if (j < HWP) {
                float x = px[j], y = py[j], z = pz[j];
                float sj  = fmaf(z, z, fmaf(y, y, x*x));
                float dot = fmaf(qz, z, fmaf(qy, y, qx*x));
                float f = fmaxf(qs + sj - 2.0f*dot, 0.0f);
                d[t] = __float_as_uint(f);
            } else {
                d[t] = 0x7f800000u;
            }
        }

        unsigned T = 0;
        for (int bit = 30; bit >= 0; --bit) {
            unsigned cand = T | (1u << bit);
            int c = 0;
            #pragma unroll
            for (int t = 0; t < 15; ++t) c += (d[t] < cand) ? 1 : 0;
            c = __reduce_add_sync(0xffffffffu, c);
            int par = bit & 1;
            if ((tid & 31) == 0) warp_sums[par][tid >> 5] = c;
            __syncthreads();
            int tot = 0;
            #pragma unroll
            for (int w = 0; w < 8; ++w) tot += warp_sums[par][w];
            if (tot < KNN) T = cand;
        }

        __syncthreads();
        if (tid == 0) { s_less = 0; s_eqn = 0; }
        __syncthreads();

        int* outp = idx_out + (n*HWP + row)*KNN;
        #pragma unroll
        for (int t = 0; t < 15; ++t) {
            int j = t*256 + tid;
            unsigned dv = d[t];
            if (dv < T) {
                int pos = atomicAdd(&s_less, 1);
                outp[pos] = j;
            } else if (dv == T && j < HWP) {
                int pos = atomicAdd(&s_eqn, 1);
                if (pos < 256) s_tie[pos] = j;
            }
        }
        __syncthreads();
        if (tid == 0) {
            int slots = KNN - s_less;
            int en = s_eqn < 256 ? s_eqn : 256;
            for (int q = 0; q < slots; ++q) {
                int best = 0x7fffffff, bi = 0;
                for (int e = 0; e < en; ++e)
                    if (s_tie[e] < best) { best = s_tie[e]; bi = e; }
                s_tie[bi] = 0x7fffffff;
                outp[s_less + q] = best;
            }
        }
        __syncthreads();
    }
}

// ---------------- gather-mean: msg = mean_k m[idx]; emits bf16 split -------
__global__ void __launch_bounds__(512) gather_mean_kernel(const float* __restrict__ m,
                                                          const int* __restrict__ idx)
{
    __shared__ int sidx[8*KNN];
    int tid = threadIdx.x;
    int s0 = blockIdx.x * 8;
    sidx[tid] = idx[s0*KNN + tid];
    __syncthreads();

    int lp = tid >> 6;
    int c4 = tid & 63;
    int s  = s0 + lp;
    int base = (s / HWP) * HWP;
    const float4* m4 = reinterpret_cast<const float4*>(m);
    const int* ip = sidx + lp*KNN;

    float4 a0 = make_float4(0,0,0,0), a1 = a0, a2 = a0, a3 = a0;
    #pragma unroll
    for (int k = 0; k < KNN; k += 4) {
        int j0 = ip[k], j1 = ip[k+1], j2 = ip[k+2], j3 = ip[k+3];
        float4 v0 = m4[(size_t)(base + j0)*64 + c4];
        float4 v1 = m4[(size_t)(base + j1)*64 + c4];
        float4 v2 = m4[(size_t)(base + j2)*64 + c4];
        float4 v3 = m4[(size_t)(base + j3)*64 + c4];
        a0.x += v0.x; a0.y += v0.y; a0.z += v0.z; a0.w += v0.w;
        a1.x += v1.x; a1.y += v1.y; a1.z += v1.z; a1.w += v1.w;
        a2.x += v2.x; a2.y += v2.y; a2.z += v2.z; a2.w += v2.w;
        a3.x += v3.x; a3.y += v3.y; a3.z += v3.z; a3.w += v3.w;
    }
    const float inv = 1.0f / 64.0f;
    float4 r;
    r.x = (a0.x + a1.x + a2.x + a3.x) * inv;
    r.y = (a0.y + a1.y + a2.y + a3.y) * inv;
    r.z = (a0.z + a1.z + a2.z + a3.z) * inv;
    r.w = (a0.w + a1.w + a2.w + a3.w) * inv;

    __nv_bfloat16 hx, lx, hy, ly, hz, lz, hw, lw;
    bsplit(r.x, hx, lx); bsplit(r.y, hy, ly);
    bsplit(r.z, hz, lz); bsplit(r.w, hw, lw);
    int o = s*CDIM + c4*4;
    *(__nv_bfloat162*)(g_Mh + o)     = __nv_bfloat162(hx, hy);
    *(__nv_bfloat162*)(g_Mh + o + 2) = __nv_bfloat162(hz, hw);
    *(__nv_bfloat162*)(g_Ml + o)     = __nv_bfloat162(lx, ly);
    *(__nv_bfloat162*)(g_Ml + o + 2) = __nv_bfloat162(lz, lw);
}

// ---------------- launcher --------------------------------------------------
extern "C" void kernel_launch(void* const* d_in, const int* in_sizes, int n_in,
                              void* d_out, int out_size)
{
    const float* cnn   = (const float*)d_in[0];
    const float* pts   = (const float*)d_in[1];
    const float* mlp_w = (const float*)d_in[2];
    const float* mlp_b = (const float*)d_in[3];
    const float* rnn_w = (const float*)d_in[4];
    const float* rnn_b = (const float*)d_in[5];
    float* out = (float*)d_out;

    float *m, *tmp, *h;
    int* idx;
    cudaGetSymbolAddress((void**)&m,   g_m);
    cudaGetSymbolAddress((void**)&tmp, g_tmp);
    cudaGetSymbolAddress((void**)&h,   g_h);
    cudaGetSymbolAddress((void**)&idx, g_idx);

    cudaFuncSetAttribute(gemm1_kernel, cudaFuncAttributeMaxDynamicSharedMemorySize, GEMM_SMEM);
    cudaFuncSetAttribute(gemm3_kernel, cudaFuncAttributeMaxDynamicSharedMemorySize, GEMM_SMEM);

    wconv_kernel<<<768, 256>>>(mlp_w, rnn_w);
    init_kernel<<<(NBATCH*CDIM*HWP)/256, 256>>>(cnn, out);
    pad_kernel<<<96, 256>>>();
    knn_kernel<<<NBATCH*(HWP/KNN_BR), 256>>>(pts, idx);

    for (int it = 0; it < 3; ++it) {
        gemm1_kernel<<<dim3(MPAD/128, 8), 256, GEMM_SMEM>>>(mlp_b, m, tmp);
        gather_mean_kernel<<<M_TOTAL/8, 512>>>(m, idx);
        gemm3_kernel<<<dim3(MPAD/128, 4), 256, GEMM_SMEM>>>(rnn_b, tmp, h);
    }
    final_kernel<<<(NBATCH*CDIM*HWP)/256, 256>>>(h, out);
}

// round 5
// speedup vs baseline: 1.3840x; 1.0278x over previous
#include <cuda_runtime.h>
#include <cuda_bf16.h>
#include <cstdint>

#define HWP 3600
#define NBATCH 2
#define CDIM 256
#define KNN 64
#define M_TOTAL (NBATCH*HWP)   // 7200
#define MPAD 7296              // padded rows (multiple of 128)

// ---------------- scratch (device globals; no allocation allowed) ----------
__device__ float g_m[MPAD*CDIM];        // relu(mlp(h)) fp32
__device__ float g_tmp[MPAD*CDIM];      // h @ Wa^T fp32
__device__ float g_h[MPAD*CDIM];        // fp32 h (for final readout)
__device__ __nv_bfloat16 g_Ah[MPAD*CDIM], g_Al[MPAD*CDIM];   // h split
__device__ __nv_bfloat16 g_Mh[MPAD*CDIM], g_Ml[MPAD*CDIM];   // msg split
__device__ __nv_bfloat16 g_Wmh[CDIM*CDIM], g_Wml[CDIM*CDIM]; // mlp_w split
__device__ __nv_bfloat16 g_Wah[CDIM*CDIM], g_Wal[CDIM*CDIM]; // rnn_w[:, :C]
__device__ __nv_bfloat16 g_Wbh[CDIM*CDIM], g_Wbl[CDIM*CDIM]; // rnn_w[:, C:]
__device__ int   g_idx[M_TOTAL*KNN];

__device__ __forceinline__ float4 ld4(const float* p){ return *reinterpret_cast<const float4*>(p); }
__device__ __forceinline__ void st4(float* p, float4 v){ *reinterpret_cast<float4*>(p) = v; }

__device__ __forceinline__ void bsplit(float v, __nv_bfloat16& h, __nv_bfloat16& l){
    h = __float2bfloat16(v);
    l = __float2bfloat16(v - __bfloat162float(h));
}

__device__ __forceinline__ uint32_t smem_u32(const void* p) {
    uint32_t a;
    asm("{ .reg .u64 t; cvta.to.shared.u64 t, %1; cvt.u32.u64 %0, t; }" : "=r"(a) : "l"(p));
    return a;
}

// ---------------- mma.sync helpers (suffix-neutral PTX, tensor pipe) -------
__device__ __forceinline__ void ldmat4(uint32_t r[4], uint32_t addr){
    asm volatile("ldmatrix.sync.aligned.m8n8.x4.shared.b16 {%0,%1,%2,%3}, [%4];"
        : "=r"(r[0]), "=r"(r[1]), "=r"(r[2]), "=r"(r[3]) : "r"(addr));
}
__device__ __forceinline__ void mma16816(float c[4], const uint32_t a[4],
                                         uint32_t b0, uint32_t b1){
    asm volatile("mma.sync.aligned.m16n8k16.row.col.f32.bf16.bf16.f32 "
        "{%0,%1,%2,%3}, {%4,%5,%6,%7}, {%8,%9}, {%0,%1,%2,%3};"
        : "+f"(c[0]), "+f"(c[1]), "+f"(c[2]), "+f"(c[3])
        : "r"(a[0]), "r"(a[1]), "r"(a[2]), "r"(a[3]), "r"(b0), "r"(b1));
}

// smem tile layout: padded stride 72 bf16 (144B = 9 x 16B -> conflict-free)
#define ASTRIDE 72
#define OFF_AH  0
#define OFF_AL  18432
#define OFF_BH  36864
#define OFF_BL  46080
#define GEMM_SMEM 55296

// ---- 128x64x256 tile: bf16 3-term split via mma.sync, fp32 accumulate -----
__device__ void tile_mma(const __nv_bfloat16* __restrict__ Ah,
                         const __nv_bfloat16* __restrict__ Al,
                         const __nv_bfloat16* __restrict__ Bh,
                         const __nv_bfloat16* __restrict__ Bl,
                         int m0, float acc[2][4][4])
{
    extern __shared__ char smem[];
    const uint32_t sb = smem_u32(smem);
    const int tid = threadIdx.x;
    const int lane = tid & 31;
    const int wid = tid >> 5;
    const int wm = wid & 3;        // m32 section
    const int wn = wid >> 2;       // n32 section

    #pragma unroll
    for (int mt = 0; mt < 2; ++mt)
        #pragma unroll
        for (int nt = 0; nt < 4; ++nt)
            #pragma unroll
            for (int q = 0; q < 4; ++q) acc[mt][nt][q] = 0.f;

    const uint32_t aoff = (uint32_t)(((lane & 15)*ASTRIDE + (lane >> 4)*8) * 2);
    const uint32_t boff = (uint32_t)((((lane & 7) + ((lane >> 4) << 3))*ASTRIDE
                                      + ((lane >> 3) & 1)*8) * 2);

    #pragma unroll 1
    for (int kc = 0; kc < 4; ++kc) {
        #pragma unroll
        for (int i = 0; i < 12; ++i) {
            int v = tid + i*256;
            const uint4* src;
            uint32_t dst;
            if (v < 1024) {
                int row = v >> 3, c8 = v & 7;
                src = (const uint4*)(Ah + (m0 + row)*CDIM + kc*64 + c8*8);
                dst = OFF_AH + (uint32_t)(row*ASTRIDE + c8*8)*2;
            } else if (v < 2048) {
                int u = v - 1024, row = u >> 3, c8 = u & 7;
                src = (const uint4*)(Al + (m0 + row)*CDIM + kc*64 + c8*8);
                dst = OFF_AL + (uint32_t)(row*ASTRIDE + c8*8)*2;
            } else if (v < 2560) {
                int u = v - 2048, row = u >> 3, c8 = u & 7;
                src = (const uint4*)(Bh + row*CDIM + kc*64 + c8*8);
                dst = OFF_BH + (uint32_t)(row*ASTRIDE + c8*8)*2;
            } else {
                int u = v - 2560, row = u >> 3, c8 = u & 7;
                src = (const uint4*)(Bl + row*CDIM + kc*64 + c8*8);
                dst = OFF_BL + (uint32_t)(row*ASTRIDE + c8*8)*2;
            }
            *(uint4*)(smem + dst) = *src;
        }
        __syncthreads();

        #pragma unroll
        for (int ks = 0; ks < 4; ++ks) {
            const uint32_t abase = (uint32_t)((wm*32*ASTRIDE + ks*16) * 2);
            const uint32_t bbase = (uint32_t)((wn*32*ASTRIDE + ks*16) * 2);
            const uint32_t mstep = (uint32_t)(16*ASTRIDE*2);

            uint32_t ah0[4], ah1[4], al0[4], al1[4];
            ldmat4(ah0, sb + OFF_AH + abase + aoff);
            ldmat4(ah1, sb + OFF_AH + abase + mstep + aoff);
            ldmat4(al0, sb + OFF_AL + abase + aoff);
            ldmat4(al1, sb + OFF_AL + abase + mstep + aoff);

            uint32_t bhA[4], bhB[4], blA[4], blB[4];
            ldmat4(bhA, sb + OFF_BH + bbase + boff);
            ldmat4(bhB, sb + OFF_BH + bbase + mstep + boff);
            ldmat4(blA, sb + OFF_BL + bbase + boff);
            ldmat4(blB, sb + OFF_BL + bbase + mstep + boff);

            mma16816(acc[0][0], ah0, bhA[0], bhA[1]);
            mma16816(acc[0][1], ah0, bhA[2], bhA[3]);
            mma16816(acc[0][2], ah0, bhB[0], bhB[1]);
            mma16816(acc[0][3], ah0, bhB[2], bhB[3]);
            mma16816(acc[1][0], ah1, bhA[0], bhA[1]);
            mma16816(acc[1][1], ah1, bhA[2], bhA[3]);
            mma16816(acc[1][2], ah1, bhB[0], bhB[1]);
            mma16816(acc[1][3], ah1, bhB[2], bhB[3]);

            mma16816(acc[0][0], ah0, blA[0], blA[1]);
            mma16816(acc[0][1], ah0, blA[2], blA[3]);
            mma16816(acc[0][2], ah0, blB[0], blB[1]);
            mma16816(acc[0][3], ah0, blB[2], blB[3]);
            mma16816(acc[1][0], ah1, blA[0], blA[1]);
            mma16816(acc[1][1], ah1, blA[2], blA[3]);
            mma16816(acc[1][2], ah1, blB[0], blB[1]);
            mma16816(acc[1][3], ah1, blB[2], blB[3]);

            mma16816(acc[0][0], al0, bhA[0], bhA[1]);
            mma16816(acc[0][1], al0, bhA[2], bhA[3]);
            mma16816(acc[0][2], al0, bhB[0], bhB[1]);
            mma16816(acc[0][3], al0, bhB[2], bhB[3]);
            mma16816(acc[1][0], al1, bhA[0], bhA[1]);
            mma16816(acc[1][1], al1, bhA[2], bhA[3]);
            mma16816(acc[1][2], al1, bhB[0], bhB[1]);
            mma16816(acc[1][3], al1, bhB[2], bhB[3]);
        }
        __syncthreads();
    }
}

// GEMM1: by 0..3 -> m = relu(h Wmlp^T + b);  by 4..7 -> tmp = h Wa^T
__global__ void __launch_bounds__(256) gemm1_kernel(const float* __restrict__ mlp_b,
                                                    float* __restrict__ m_out,
                                                    float* __restrict__ tmp_out)
{
    int m0 = blockIdx.x * 128;
    int by = blockIdx.y;
    bool is_m = by < 4;
    int d0 = (is_m ? by : by - 4) * 64;
    const __nv_bfloat16* Bh = (is_m ? g_Wmh : g_Wah) + d0*CDIM;
    const __nv_bfloat16* Bl = (is_m ? g_Wml : g_Wal) + d0*CDIM;

    float acc[2][4][4];
    tile_mma(g_Ah, g_Al, Bh, Bl, m0, acc);

    int lane = threadIdx.x & 31, wid = threadIdx.x >> 5;
    int wm = wid & 3, wn = wid >> 2;
    int g = lane >> 2, t = lane & 3;

    #pragma unroll
    for (int mt = 0; mt < 2; ++mt) {
        #pragma unroll
        for (int nt = 0; nt < 4; ++nt) {
            int nl = wn*32 + nt*8 + t*2;
            int n = d0 + nl;
            float bx = 0.f, byv = 0.f;
            if (is_m) { bx = mlp_b[n]; byv = mlp_b[n+1]; }
            #pragma unroll
            for (int half = 0; half < 2; ++half) {
                int m = m0 + wm*32 + mt*16 + g + half*8;
                if (m >= M_TOTAL) continue;
                float vx = acc[mt][nt][half*2+0];
                float vy = acc[mt][nt][half*2+1];
                if (is_m) {
                    vx = fmaxf(vx + bx, 0.f);
                    vy = fmaxf(vy + byv, 0.f);
                    *(float2*)(m_out + m*CDIM + n) = make_float2(vx, vy);
                } else {
                    *(float2*)(tmp_out + m*CDIM + n) = make_float2(vx, vy);
                }
            }
        }
    }
}

// GEMM3: h' = relu(tmp + msg Wb^T + b_rnn); writes fp32 h and bf16 split
__global__ void __launch_bounds__(256) gemm3_kernel(const float* __restrict__ rnn_b,
                                                    const float* __restrict__ tmp,
                                                    float* __restrict__ h_out)
{
    int m0 = blockIdx.x * 128;
    int d0 = blockIdx.y * 64;

    float acc[2][4][4];
    tile_mma(g_Mh, g_Ml, g_Wbh + d0*CDIM, g_Wbl + d0*CDIM, m0, acc);

    int lane = threadIdx.x & 31, wid = threadIdx.x >> 5;
    int wm = wid & 3, wn = wid >> 2;
    int g = lane >> 2, t = lane & 3;

    #pragma unroll
    for (int mt = 0; mt < 2; ++mt) {
        #pragma unroll
        for (int nt = 0; nt < 4; ++nt) {
            int n = d0 + wn*32 + nt*8 + t*2;
            float bx = rnn_b[n], byv = rnn_b[n+1];
            #pragma unroll
            for (int half = 0; half < 2; ++half) {
                int m = m0 + wm*32 + mt*16 + g + half*8;
                if (m >= M_TOTAL) continue;
                float2 tv = *(const float2*)(tmp + m*CDIM + n);
                float vx = fmaxf(acc[mt][nt][half*2+0] + tv.x + bx, 0.f);
                float vy = fmaxf(acc[mt][nt][half*2+1] + tv.y + byv, 0.f);
                *(float2*)(h_out + m*CDIM + n) = make_float2(vx, vy);
                __nv_bfloat16 hx, lx, hy, ly;
                bsplit(vx, hx, lx); bsplit(vy, hy, ly);
                *(__nv_bfloat162*)(g_Ah + m*CDIM + n) = __nv_bfloat162(hx, hy);
                *(__nv_bfloat162*)(g_Al + m*CDIM + n) = __nv_bfloat162(lx, ly);
            }
        }
    }
}

// ---------------- weight conversion (once per call) ------------------------
__global__ void __launch_bounds__(256) wconv_kernel(const float* __restrict__ mlp_w,
                                                    const float* __restrict__ rnn_w)
{
    int e = blockIdx.x * 256 + threadIdx.x;   // < 256*768
    if (e < CDIM*CDIM) {
        __nv_bfloat16 h, l; bsplit(mlp_w[e], h, l);
        g_Wmh[e] = h; g_Wml[e] = l;
    } else {
        int u = e - CDIM*CDIM;                 // < 256*512
        int r = u >> 9, c = u & 511;
        __nv_bfloat16 h, l; bsplit(rnn_w[u], h, l);
        if (c < CDIM) { g_Wah[r*CDIM + c] = h; g_Wal[r*CDIM + c] = l; }
        else          { g_Wbh[r*CDIM + c - CDIM] = h; g_Wbl[r*CDIM + c - CDIM] = l; }
    }
}

// zero padded rows of bf16 operand arrays
__global__ void __launch_bounds__(256) pad_kernel()
{
    int e = blockIdx.x * 256 + threadIdx.x;   // < 96*256
    int o = (M_TOTAL + (e >> 8))*CDIM + (e & 255);
    g_Ah[o] = __float2bfloat16(0.f); g_Al[o] = __float2bfloat16(0.f);
    g_Mh[o] = __float2bfloat16(0.f); g_Ml[o] = __float2bfloat16(0.f);
}

// ---------------- init: out[:, :256] = cnn; Ah/Al = bf16 split of NHWC h0 --
__global__ void __launch_bounds__(256) init_kernel(const float* __restrict__ cnn,
                                                   float* __restrict__ out)
{
    int e = blockIdx.x * 256 + threadIdx.x;
    int s = e % HWP;
    int c = (e / HWP) & (CDIM-1);
    int n = e / (HWP*CDIM);
    float v = cnn[e];
    out[(n*(2*CDIM) + c)*HWP + s] = v;
    __nv_bfloat16 h, l; bsplit(v, h, l);
    int o = (n*HWP + s)*CDIM + c;
    g_Ah[o] = h; g_Al[o] = l;
}

__global__ void __launch_bounds__(256) final_kernel(const float* __restrict__ h,
                                                    float* __restrict__ out)
{
    int e = blockIdx.x * 256 + threadIdx.x;
    int s = e % HWP;
    int c = (e / HWP) & (CDIM-1);
    int n = e / (HWP*CDIM);
    out[(n*(2*CDIM) + CDIM + c)*HWP + s] = h[(n*HWP + s)*CDIM + c];
}

// ---------------- KNN v2: exponent-histogram radix select ------------------
#define KNN_BR 12
#define CAND_CAP 1024
__global__ void __launch_bounds__(256) knn_kernel(const float* __restrict__ pts,
                                                  int* __restrict__ idx_out)
{
    __shared__ float px[HWP], py[HWP], pz[HWP];
    __shared__ int hist[256];
    __shared__ unsigned cand_val[CAND_CAP];
    __shared__ int cand_idx[CAND_CAP];
    __shared__ int s_tie[256];
    __shared__ int sc[6];   // 0:E_crit 1:n_below 2:cand_cnt 3:out_cnt 4:tie_cnt
    __shared__ int warp_sums[2][8];   // fallback path

    int gb = blockIdx.x;
    int n  = gb / (HWP/KNN_BR);
    int g  = gb % (HWP/KNN_BR);
    int tid = threadIdx.x;
    int lane = tid & 31, wid = tid >> 5;

    const float* p = pts + n*3*HWP;
    for (int i = tid; i < HWP; i += 256) {
        px[i] = p[i];
        py[i] = p[i + HWP];
        pz[i] = p[i + 2*HWP];
    }
    __syncthreads();

    for (int r = 0; r < KNN_BR; ++r) {
        int row = g*KNN_BR + r;
        float qx = px[row], qy = py[row], qz = pz[row];
        float qs = fmaf(qz, qz, fmaf(qy, qy, qx*qx));

        unsigned d[15];
        #pragma unroll
        for (int t = 0; t < 15; ++t) {
            int j = t*256 + tid;
            if (j < HWP) {
                float x = px[j], y = py[j], z = pz[j];
                float sj  = fmaf(z, z, fmaf(y, y, x*x));
                float dot = fmaf(qz, z, fmaf(qy, y, qx*x));
                d[t] = __float_as_uint(fmaxf(qs + sj - 2.0f*dot, 0.0f));
            } else {
                d[t] = 0x7f800000u;   // +inf pad -> bin 255, never selected
            }
        }

        hist[tid] = 0;
        if (tid == 0) { sc[2] = 0; sc[3] = 0; sc[4] = 0; }
        __syncthreads();

        // exponent histogram, warp-aggregated (one atomic per distinct bin/warp)
        #pragma unroll
        for (int t = 0; t < 15; ++t) {
            unsigned e = d[t] >> 23;
            unsigned mask = __match_any_sync(0xffffffffu, e);
            int leader = __ffs(mask) - 1;
            if (lane == leader) atomicAdd(&hist[e], __popc(mask));
        }
        __syncthreads();

        // warp 0: prefix scan -> critical bin
        if (wid == 0) {
            int base = lane*8, loc[8], ssum = 0;
            #pragma unroll
            for (int j2 = 0; j2 < 8; ++j2) { loc[j2] = hist[base+j2]; ssum += loc[j2]; }
            int pre = ssum;
            #pragma unroll
            for (int o = 1; o < 32; o <<= 1) {
                int v = __shfl_up_sync(0xffffffffu, pre, o);
                if (lane >= o) pre += v;
            }
            int excl = pre - ssum;
            if (excl < KNN && excl + ssum >= KNN) {   // unique crossing lane
                int cum = excl;
                #pragma unroll
                for (int j2 = 0; j2 < 8; ++j2) {
                    if (cum + loc[j2] >= KNN) { sc[0] = base + j2; sc[1] = cum; break; }
                    cum += loc[j2];
                }
            }
        }
        __syncthreads();
        int E_crit = sc[0], n_below = sc[1];

        int* outp = idx_out + (n*HWP + row)*KNN;

        // compact: exp < E_crit are winners; exp == E_crit are candidates
        #pragma unroll
        for (int t = 0; t < 15; ++t) {
            int e = (int)(d[t] >> 23);
            int j = t*256 + tid;
            if (e < E_crit) {
                int pos = atomicAdd(&sc[3], 1);
                outp[pos] = j;
            } else if (e == E_crit) {
                int pos = atomicAdd(&sc[2], 1);
                if (pos < CAND_CAP) { cand_val[pos] = d[t]; cand_idx[pos] = j; }
            }
        }
        __syncthreads();
        int c = sc[2], Kp = KNN - n_below;

        if (c == Kp) {
            for (int i = tid; i < c; i += 256) outp[n_below + i] = cand_idx[i];
        } else if (c <= CAND_CAP) {
            if (wid == 0) {
                // 23-bit search within the critical bin, warp-local
                unsigned T = ((unsigned)E_crit) << 23;
                for (int bit = 22; bit >= 0; --bit) {
                    unsigned candv = T | (1u << bit);
                    int cnt = 0;
                    for (int i = lane; i < c; i += 32) cnt += (cand_val[i] < candv) ? 1 : 0;
                    cnt = __reduce_add_sync(0xffffffffu, cnt);
                    if (cnt < Kp) T = candv;
                }
                for (int i = lane; i < c; i += 32) {
                    unsigned v = cand_val[i];
                    if (v < T) { int pos = atomicAdd(&sc[3], 1); outp[pos] = cand_idx[i]; }
                    else if (v == T) { int pos = atomicAdd(&sc[4], 1); if (pos < 256) s_tie[pos] = cand_idx[i]; }
                }
                __syncwarp();
                if (lane == 0) {
                    int slots = KNN - sc[3];
                    int en = sc[4] < 256 ? sc[4] : 256;
                    int ob = sc[3];
                    for (int q2 = 0; q2 < slots; ++q2) {
                        int best = 0x7fffffff, bi = 0;
                        for (int e2 = 0; e2 < en; ++e2)
                            if (s_tie[e2] < best) { best = s_tie[e2]; bi = e2; }
                        s_tie[bi] = 0x7fffffff;
                        outp[ob + q2] = best;
                    }
                }
            }
        } else {
            // fallback: old block-wide 31-bit search (always correct; ~never hit)
            if (tid == 0) { sc[3] = 0; sc[4] = 0; }
            __syncthreads();
            unsigned T = 0;
            for (int bit = 30; bit >= 0; --bit) {
                unsigned candv = T | (1u << bit);
                int cc = 0;
                #pragma unroll
                for (int t = 0; t < 15; ++t) cc += (d[t] < candv) ? 1 : 0;
                cc = __reduce_add_sync(0xffffffffu, cc);
                int par = bit & 1;
                if (lane == 0) warp_sums[par][wid] = cc;
                __syncthreads();
                int tot = 0;
                #pragma unroll
                for (int w = 0; w < 8; ++w) tot += warp_sums[par][w];
                if (tot < KNN) T = candv;
            }
            __syncthreads();
            #pragma unroll
            for (int t = 0; t < 15; ++t) {
                int j = t*256 + tid;
                unsigned dv = d[t];
                if (dv < T) { int pos = atomicAdd(&sc[3], 1); outp[pos] = j; }
                else if (dv == T && j < HWP) { int pos = atomicAdd(&sc[4], 1); if (pos < 256) s_tie[pos] = j; }
            }
            __syncthreads();
            if (tid == 0) {
                int slots = KNN - sc[3];
                int en = sc[4] < 256 ? sc[4] : 256;
                int ob = sc[3];
                for (int q2 = 0; q2 < slots; ++q2) {
                    int best = 0x7fffffff, bi = 0;
                    for (int e2 = 0; e2 < en; ++e2)
                        if (s_tie[e2] < best) { best = s_tie[e2]; bi = e2; }
                    s_tie[bi] = 0x7fffffff;
                    outp[ob + q2] = best;
                }
            }
        }
        __syncthreads();
    }
}

// ---------------- gather-mean: msg = mean_k m[idx]; emits bf16 split -------
__global__ void __launch_bounds__(512) gather_mean_kernel(const float* __restrict__ m,
                                                          const int* __restrict__ idx)
{
    __shared__ int sidx[8*KNN];
    int tid = threadIdx.x;
    int s0 = blockIdx.x * 8;
    sidx[tid] = idx[s0*KNN + tid];
    __syncthreads();

    int lp = tid >> 6;
    int c4 = tid & 63;
    int s  = s0 + lp;
    int base = (s / HWP) * HWP;
    const float4* m4 = reinterpret_cast<const float4*>(m);
    const int* ip = sidx + lp*KNN;

    float4 a0 = make_float4(0,0,0,0), a1 = a0, a2 = a0, a3 = a0;
    #pragma unroll
    for (int k = 0; k < KNN; k += 4) {
        int j0 = ip[k], j1 = ip[k+1], j2 = ip[k+2], j3 = ip[k+3];
        float4 v0 = m4[(size_t)(base + j0)*64 + c4];
        float4 v1 = m4[(size_t)(base + j1)*64 + c4];
        float4 v2 = m4[(size_t)(base + j2)*64 + c4];
        float4 v3 = m4[(size_t)(base + j3)*64 + c4];
        a0.x += v0.x; a0.y += v0.y; a0.z += v0.z; a0.w += v0.w;
        a1.x += v1.x; a1.y += v1.y; a1.z += v1.z; a1.w += v1.w;
        a2.x += v2.x; a2.y += v2.y; a2.z += v2.z; a2.w += v2.w;
        a3.x += v3.x; a3.y += v3.y; a3.z += v3.z; a3.w += v3.w;
    }
    const float inv = 1.0f / 64.0f;
    float4 r;
    r.x = (a0.x + a1.x + a2.x + a3.x) * inv;
    r.y = (a0.y + a1.y + a2.y + a3.y) * inv;
    r.z = (a0.z + a1.z + a2.z + a3.z) * inv;
    r.w = (a0.w + a1.w + a2.w + a3.w) * inv;

    __nv_bfloat16 hx, lx, hy, ly, hz, lz, hw, lw;
    bsplit(r.x, hx, lx); bsplit(r.y, hy, ly);
    bsplit(r.z, hz, lz); bsplit(r.w, hw, lw);
    int o = s*CDIM + c4*4;
    *(__nv_bfloat162*)(g_Mh + o)     = __nv_bfloat162(hx, hy);
    *(__nv_bfloat162*)(g_Mh + o + 2) = __nv_bfloat162(hz, hw);
    *(__nv_bfloat162*)(g_Ml + o)     = __nv_bfloat162(lx, ly);
    *(__nv_bfloat162*)(g_Ml + o + 2) = __nv_bfloat162(lz, lw);
}

// ---------------- launcher --------------------------------------------------
extern "C" void kernel_launch(void* const* d_in, const int* in_sizes, int n_in,
                              void* d_out, int out_size)
{
    const float* cnn   = (const float*)d_in[0];
    const float* pts   = (const float*)d_in[1];
    const float* mlp_w = (const float*)d_in[2];
    const float* mlp_b = (const float*)d_in[3];
    const float* rnn_w = (const float*)d_in[4];
    const float* rnn_b = (const float*)d_in[5];
    float* out = (float*)d_out;

    float *m, *tmp, *h;
    int* idx;
    cudaGetSymbolAddress((void**)&m,   g_m);
    cudaGetSymbolAddress((void**)&tmp, g_tmp);
    cudaGetSymbolAddress((void**)&h,   g_h);
    cudaGetSymbolAddress((void**)&idx, g_idx);

    cudaFuncSetAttribute(gemm1_kernel, cudaFuncAttributeMaxDynamicSharedMemorySize, GEMM_SMEM);
    cudaFuncSetAttribute(gemm3_kernel, cudaFuncAttributeMaxDynamicSharedMemorySize, GEMM_SMEM);

    wconv_kernel<<<768, 256>>>(mlp_w, rnn_w);
    init_kernel<<<(NBATCH*CDIM*HWP)/256, 256>>>(cnn, out);
    pad_kernel<<<96, 256>>>();
    knn_kernel<<<NBATCH*(HWP/KNN_BR), 256>>>(pts, idx);

    for (int it = 0; it < 3; ++it) {
        gemm1_kernel<<<dim3(MPAD/128, 8), 256, GEMM_SMEM>>>(mlp_b, m, tmp);
        gather_mean_kernel<<<M_TOTAL/8, 512>>>(m, idx);
        gemm3_kernel<<<dim3(MPAD/128, 4), 256, GEMM_SMEM>>>(rnn_b, tmp, h);
    }
    final_kernel<<<(NBATCH*CDIM*HWP)/256, 256>>>(h, out);
}